// round 6
// baseline (speedup 1.0000x reference)
#include <cuda_runtime.h>
#include <cstdint>

// ---------------- problem constants ----------------
#define IN_SZ    64
#define HID      128
#define OUT_SZ   64
#define NHEAD    16
#define MT       128          // batch rows per rep
#define REPS     8            // 1024 rows per CTA
#define NTHREADS 256          // 8 warps: mg = wid&3 (32-row group), nh = wid>>2

// ---------------- smem layout (u32 offsets) ----------------
// all fp16 operand buffers row-major with pitch % 8 == 4 (conflict-free frags)
#define XT_U    0             // x tile:  128 rows x 36 (32 data u32 = 64 halves)
#define HT_U    4608          // h tile:  128 rows x 68 (64 data u32 = 128 halves)
#define W1T_U   13312         // W1^T:    128 rows(n) x 36 (64 k halves)
#define W2T_U   17920         // W2^T:     64 rows(n) x 68 (128 k halves)
#define B1S_U   22272         // 128 f32
#define B2S_U   22400         // 64 f32
#define SMEM_U  22464
#define SMEM_BYTES (SMEM_U * 4)   // 89856 B -> 2 CTAs/SM

#define XP      36
#define HP      68

// ---------------- helpers ----------------
// pack two f32 -> f16x2 (lo = a, hi = b)
__device__ __forceinline__ uint32_t p2(float a, float b) {
    uint32_t r;
    asm("cvt.rn.f16x2.f32 %0, %1, %2;" : "=r"(r) : "f"(b), "f"(a));
    return r;
}

// D += A * B  (f16 m16n8k16, row.col, fp32 accum)
__device__ __forceinline__ void mma16(float c[4], const uint4 a, const uint2 b) {
    asm volatile(
        "mma.sync.aligned.m16n8k16.row.col.f32.f16.f16.f32 "
        "{%0,%1,%2,%3}, {%4,%5,%6,%7}, {%8,%9}, {%0,%1,%2,%3};\n"
        : "+f"(c[0]), "+f"(c[1]), "+f"(c[2]), "+f"(c[3])
        : "r"(a.x), "r"(a.y), "r"(a.z), "r"(a.w), "r"(b.x), "r"(b.y));
}

__device__ __forceinline__ float eluf(float v) {
    return v > 0.0f ? v : (__expf(v) - 1.0f);
}

// ---------------- kernel ----------------
__global__ void __launch_bounds__(NTHREADS, 2)
mlp16_kernel(const float* __restrict__ x,
             const float* __restrict__ W1,
             const float* __restrict__ b1,
             const float* __restrict__ W2,
             const float* __restrict__ b2,
             float* __restrict__ out)
{
    extern __shared__ uint32_t sm[];
    float* b1s = reinterpret_cast<float*>(sm + B1S_U);
    float* b2s = reinterpret_cast<float*>(sm + B2S_U);

    const int tid = threadIdx.x;
    const int wid = tid >> 5;
    const int lid = tid & 31;
    const int g   = lid >> 2;         // 0..7
    const int tc  = lid & 3;          // 0..3
    const int mg  = wid & 3;          // rows [32mg, 32mg+32)
    const int nh  = wid >> 2;         // 0..1
    const int head = blockIdx.x;
    const size_t mbase = (size_t)blockIdx.y * (MT * REPS);

    // ---- biases ----
    if (tid < HID)    b1s[tid] = b1[head * HID + tid];
    if (tid < OUT_SZ) b2s[tid] = b2[head * OUT_SZ + tid];

    // ---- stage W1^T (fp16): Wt1[n][k], n=0..127, k=0..63 ----
    {
        const float* W1h = W1 + (size_t)head * IN_SZ * HID;
        const int n = tid & 127;
        const int ih = tid >> 7;               // 0..1
        #pragma unroll
        for (int ii = 0; ii < 8; ii++) {
            int i4 = ih * 8 + ii;              // k-group of 4: 0..15
            int k0 = i4 * 4;
            float w0 = W1h[(k0 + 0) * HID + n];
            float w1 = W1h[(k0 + 1) * HID + n];
            float w2 = W1h[(k0 + 2) * HID + n];
            float w3 = W1h[(k0 + 3) * HID + n];
            uint2 u;
            u.x = p2(w0, w1);
            u.y = p2(w2, w3);
            *reinterpret_cast<uint2*>(sm + W1T_U + n * XP + 2 * i4) = u;
        }
    }

    // ---- stage W2^T (fp16): Wt2[n][k], n=0..63, k=0..127 ----
    {
        const float* W2h = W2 + (size_t)head * HID * OUT_SZ;
        const int n = tid & 63;
        const int jh = tid >> 6;               // 0..3
        #pragma unroll
        for (int jj = 0; jj < 8; jj++) {
            int j4 = jh * 8 + jj;              // k-group of 4: 0..31
            int k0 = j4 * 4;
            float w0 = W2h[(k0 + 0) * OUT_SZ + n];
            float w1 = W2h[(k0 + 1) * OUT_SZ + n];
            float w2 = W2h[(k0 + 2) * OUT_SZ + n];
            float w3 = W2h[(k0 + 3) * OUT_SZ + n];
            uint2 u;
            u.x = p2(w0, w1);
            u.y = p2(w2, w3);
            *reinterpret_cast<uint2*>(sm + W2T_U + n * HP + 2 * j4) = u;
        }
    }

    #pragma unroll 1
    for (int rep = 0; rep < REPS; rep++) {
        // ---- stage x tile [128 x 64] -> fp16 rows, pitch XP ----
        {
            const float4* xt = reinterpret_cast<const float4*>(
                x + (mbase + (size_t)rep * MT) * IN_SZ);
            #pragma unroll
            for (int it = 0; it < 4; it++) {
                int task = it * NTHREADS + tid;       // 0..1023
                int row = task >> 3;
                int q   = task & 7;                   // 8-col group
                float4 v0 = xt[row * 16 + 2 * q];
                float4 v1 = xt[row * 16 + 2 * q + 1];
                uint4 u;
                u.x = p2(v0.x, v0.y);
                u.y = p2(v0.z, v0.w);
                u.z = p2(v1.x, v1.y);
                u.w = p2(v1.z, v1.w);
                *reinterpret_cast<uint4*>(sm + XT_U + row * XP + 4 * q) = u;
            }
        }
        __syncthreads();   // (1) x + (rep0: W) visible; prior-rep GEMM2 done

        // ---- GEMM1: warp = rows [32mg,+32) x hid cols [64nh,+64), K=64 ----
        float C1[2][8][4];
        #pragma unroll
        for (int mt = 0; mt < 2; mt++)
            #pragma unroll
            for (int t1 = 0; t1 < 8; t1++)
                #pragma unroll
                for (int r = 0; r < 4; r++) C1[mt][t1][r] = 0.0f;

        #pragma unroll
        for (int s = 0; s < 4; s++) {          // k16 steps
            uint4 A[2];
            #pragma unroll
            for (int mt = 0; mt < 2; mt++) {
                int r0 = mg * 32 + mt * 16;
                A[mt].x = sm[XT_U + (r0 + g) * XP + 8 * s + tc];
                A[mt].y = sm[XT_U + (r0 + 8 + g) * XP + 8 * s + tc];
                A[mt].z = sm[XT_U + (r0 + g) * XP + 8 * s + tc + 4];
                A[mt].w = sm[XT_U + (r0 + 8 + g) * XP + 8 * s + tc + 4];
            }
            #pragma unroll
            for (int t1 = 0; t1 < 8; t1++) {
                int n0 = nh * 64 + t1 * 8;
                uint2 Bv;
                Bv.x = sm[W1T_U + (n0 + g) * XP + 8 * s + tc];
                Bv.y = sm[W1T_U + (n0 + g) * XP + 8 * s + tc + 4];
                mma16(C1[0][t1], A[0], Bv);
                mma16(C1[1][t1], A[1], Bv);
            }
        }

        // ---- epilogue1: bias + ELU -> fp16 -> Ht (conflict-free) ----
        #pragma unroll
        for (int mt = 0; mt < 2; mt++) {
            int r0 = mg * 32 + mt * 16;
            #pragma unroll
            for (int t1 = 0; t1 < 8; t1++) {
                int colA = nh * 64 + t1 * 8 + 2 * tc;
                float bA = b1s[colA], bB = b1s[colA + 1];
                float v0 = eluf(C1[mt][t1][0] + bA);
                float v1 = eluf(C1[mt][t1][1] + bB);
                float v2 = eluf(C1[mt][t1][2] + bA);
                float v3 = eluf(C1[mt][t1][3] + bB);
                int cu = nh * 32 + t1 * 4 + tc;        // u32 col in Ht
                sm[HT_U + (r0 + g) * HP + cu]     = p2(v0, v1);
                sm[HT_U + (r0 + 8 + g) * HP + cu] = p2(v2, v3);
            }
        }
        __syncthreads();   // (2) Ht complete

        // ---- GEMM2: warp = rows [32mg,+32) x out cols [32nh,+32), K=128 ----
        float C2[2][4][4];
        #pragma unroll
        for (int mt = 0; mt < 2; mt++)
            #pragma unroll
            for (int t2 = 0; t2 < 4; t2++)
                #pragma unroll
                for (int r = 0; r < 4; r++) C2[mt][t2][r] = 0.0f;

        #pragma unroll
        for (int s = 0; s < 8; s++) {          // k16 steps
            uint4 A[2];
            #pragma unroll
            for (int mt = 0; mt < 2; mt++) {
                int r0 = mg * 32 + mt * 16;
                A[mt].x = sm[HT_U + (r0 + g) * HP + 8 * s + tc];
                A[mt].y = sm[HT_U + (r0 + 8 + g) * HP + 8 * s + tc];
                A[mt].z = sm[HT_U + (r0 + g) * HP + 8 * s + tc + 4];
                A[mt].w = sm[HT_U + (r0 + 8 + g) * HP + 8 * s + tc + 4];
            }
            #pragma unroll
            for (int t2 = 0; t2 < 4; t2++) {
                int n0 = nh * 32 + t2 * 8;
                uint2 Bv;
                Bv.x = sm[W2T_U + (n0 + g) * HP + 8 * s + tc];
                Bv.y = sm[W2T_U + (n0 + g) * HP + 8 * s + tc + 4];
                mma16(C2[0][t2], A[0], Bv);
                mma16(C2[1][t2], A[1], Bv);
            }
        }

        // ---- epilogue2: + b2 -> out[b, head, :] ----
        #pragma unroll
        for (int mt = 0; mt < 2; mt++) {
            const size_t rbase = mbase + (size_t)rep * MT + mg * 32 + mt * 16 + g;
            #pragma unroll
            for (int half = 0; half < 2; half++) {
                const size_t off = (rbase + 8 * half) * (NHEAD * OUT_SZ)
                                 + (size_t)head * OUT_SZ;
                #pragma unroll
                for (int t2 = 0; t2 < 4; t2++) {
                    int col = nh * 32 + t2 * 8 + 2 * tc;
                    float2 o;
                    o.x = C2[mt][t2][half * 2 + 0] + b2s[col];
                    o.y = C2[mt][t2][half * 2 + 1] + b2s[col + 1];
                    *reinterpret_cast<float2*>(out + off + col) = o;
                }
            }
        }
        // next-rep x staging is safe: reaching it implies this warp passed
        // sync(2); all warps' x reads (GEMM1) ended before their sync(2) arrival.
    }
}

// ---------------- launch ----------------
extern "C" void kernel_launch(void* const* d_in, const int* in_sizes, int n_in,
                              void* d_out, int out_size)
{
    const float* x  = (const float*)d_in[0];
    const float* W1 = (const float*)d_in[1];
    const float* b1 = (const float*)d_in[2];
    const float* W2 = (const float*)d_in[3];
    const float* b2 = (const float*)d_in[4];
    float* out = (float*)d_out;

    int B = in_sizes[0] / IN_SZ;            // 131072
    int ytiles = B / (MT * REPS);           // 128

    cudaFuncSetAttribute(mlp16_kernel,
                         cudaFuncAttributeMaxDynamicSharedMemorySize, SMEM_BYTES);
    mlp16_kernel<<<dim3(NHEAD, ytiles), NTHREADS, SMEM_BYTES>>>(x, W1, b1, W2, b2, out);
}

// round 7
// speedup vs baseline: 1.5943x; 1.5943x over previous
#include <cuda_runtime.h>
#include <cstdint>

// ---------------- problem constants ----------------
#define IN_SZ    64
#define HID      128
#define OUT_SZ   64
#define NHEAD    16
#define MT       128          // batch rows per rep
#define REPS     4            // 512 rows per CTA
#define NTHREADS 256          // 8 warps: mg = wid&3 (32-row group), nh = wid>>2

// ---------------- smem layout (u32 offsets; pitches % 8 == 4 -> conflict-free) ----------------
#define XT_U    0             // x tile:  128 rows x 36 u32 (64 halves data)
#define HT_U    4608          // h tile:  128 rows x 68 u32 (128 halves data)
#define W1T_U   13312         // W1^T:    128 rows(n) x 36 u32 (64 k halves)
#define W2T_U   17920         // W2^T:     64 rows(n) x 68 u32 (128 k halves)
#define B1S_U   22272         // 128 f32
#define B2S_U   22400         // 64 f32
#define SMEM_U  22464
#define SMEM_BYTES (SMEM_U * 4)   // 89856 B -> 2 CTAs/SM

#define XPB     144           // x / W1T row pitch in bytes
#define HPB     272           // h / W2T row pitch in bytes
#define XP      36
#define HP      68

// ---------------- helpers ----------------
__device__ __forceinline__ uint32_t smem_u32(const void* p) {
    uint32_t a;
    asm("{ .reg .u64 t; cvta.to.shared.u64 t, %1; cvt.u32.u64 %0, t; }"
        : "=r"(a) : "l"(p));
    return a;
}

// pack two f32 -> f16x2 (lo = a, hi = b)
__device__ __forceinline__ uint32_t p2(float a, float b) {
    uint32_t r;
    asm("cvt.rn.f16x2.f32 %0, %1, %2;" : "=r"(r) : "f"(b), "f"(a));
    return r;
}

__device__ __forceinline__ void ldsm4(uint4& d, uint32_t addr) {
    asm volatile("ldmatrix.sync.aligned.m8n8.x4.shared.b16 {%0,%1,%2,%3}, [%4];"
                 : "=r"(d.x), "=r"(d.y), "=r"(d.z), "=r"(d.w) : "r"(addr));
}

// D += A * B  (f16 m16n8k16, row.col, fp32 accum)
__device__ __forceinline__ void mma16(float c[4], const uint4 a, uint32_t b0, uint32_t b1) {
    asm volatile(
        "mma.sync.aligned.m16n8k16.row.col.f32.f16.f16.f32 "
        "{%0,%1,%2,%3}, {%4,%5,%6,%7}, {%8,%9}, {%0,%1,%2,%3};\n"
        : "+f"(c[0]), "+f"(c[1]), "+f"(c[2]), "+f"(c[3])
        : "r"(a.x), "r"(a.y), "r"(a.z), "r"(a.w), "r"(b0), "r"(b1));
}

__device__ __forceinline__ float eluf(float v) {
    return v > 0.0f ? v : (__expf(v) - 1.0f);
}

// ---------------- kernel ----------------
__global__ void __launch_bounds__(NTHREADS, 2)
mlp16_kernel(const float* __restrict__ x,
             const float* __restrict__ W1,
             const float* __restrict__ b1,
             const float* __restrict__ W2,
             const float* __restrict__ b2,
             float* __restrict__ out)
{
    extern __shared__ uint32_t sm[];
    float* b1s = reinterpret_cast<float*>(sm + B1S_U);
    float* b2s = reinterpret_cast<float*>(sm + B2S_U);
    const uint32_t sb = smem_u32(sm);

    const int tid = threadIdx.x;
    const int wid = tid >> 5;
    const int lid = tid & 31;
    const int g   = lid >> 2;         // 0..7
    const int tc  = lid & 3;          // 0..3
    const int mg  = wid & 3;          // rows [32mg, 32mg+32)
    const int nh  = wid >> 2;         // 0..1
    const int head = blockIdx.x;
    const size_t mbase = (size_t)blockIdx.y * (MT * REPS);

    // ldmatrix per-lane address components
    const int arow = (lid & 7) + (lid & 8);                 // A: row within 16
    const int akb  = (lid & 16);                            // A: k-half byte off (0/16)
    const int brow = (lid & 7) + ((lid & 16) >> 1);         // B: n row within 16
    const int bkb  = (lid & 8) << 1;                        // B: k-half byte off (0/16)

    // lane-constant bases (bytes)
    const uint32_t aX  = sb + XT_U  * 4 + (mg * 32 + arow) * XPB + akb;
    const uint32_t bW1 = sb + W1T_U * 4 + (nh * 64 + brow) * XPB + bkb;
    const uint32_t aH  = sb + HT_U  * 4 + (mg * 32 + arow) * HPB + akb;
    const uint32_t bW2 = sb + W2T_U * 4 + (nh * 32 + brow) * HPB + bkb;

    // ---- biases ----
    if (tid < HID)    b1s[tid] = b1[head * HID + tid];
    if (tid < OUT_SZ) b2s[tid] = b2[head * OUT_SZ + tid];

    // ---- stage W1^T (fp16): Wt1[n][k], n=0..127, k=0..63 ----
    {
        const float* W1h = W1 + (size_t)head * IN_SZ * HID;
        const int n = tid & 127;
        const int ih = tid >> 7;               // 0..1
        #pragma unroll
        for (int ii = 0; ii < 8; ii++) {
            int i4 = ih * 8 + ii;              // k-group of 4
            int k0 = i4 * 4;
            float w0 = W1h[(k0 + 0) * HID + n];
            float w1 = W1h[(k0 + 1) * HID + n];
            float w2 = W1h[(k0 + 2) * HID + n];
            float w3 = W1h[(k0 + 3) * HID + n];
            uint2 u;
            u.x = p2(w0, w1);
            u.y = p2(w2, w3);
            *reinterpret_cast<uint2*>(sm + W1T_U + n * XP + 2 * i4) = u;
        }
    }

    // ---- stage W2^T (fp16): Wt2[n][k], n=0..63, k=0..127 ----
    {
        const float* W2h = W2 + (size_t)head * HID * OUT_SZ;
        const int n = tid & 63;
        const int jh = tid >> 6;               // 0..3
        #pragma unroll
        for (int jj = 0; jj < 8; jj++) {
            int j4 = jh * 8 + jj;
            int k0 = j4 * 4;
            float w0 = W2h[(k0 + 0) * OUT_SZ + n];
            float w1 = W2h[(k0 + 1) * OUT_SZ + n];
            float w2 = W2h[(k0 + 2) * OUT_SZ + n];
            float w3 = W2h[(k0 + 3) * OUT_SZ + n];
            uint2 u;
            u.x = p2(w0, w1);
            u.y = p2(w2, w3);
            *reinterpret_cast<uint2*>(sm + W2T_U + n * HP + 2 * j4) = u;
        }
    }

    #pragma unroll 1
    for (int rep = 0; rep < REPS; rep++) {
        // ---- stage x tile [128 x 64] -> fp16 rows, pitch XP ----
        {
            const float4* xt = reinterpret_cast<const float4*>(
                x + (mbase + (size_t)rep * MT) * IN_SZ);
            #pragma unroll
            for (int it = 0; it < 4; it++) {
                int task = it * NTHREADS + tid;       // 0..1023
                int row = task >> 3;
                int q   = task & 7;
                float4 v0 = xt[row * 16 + 2 * q];
                float4 v1 = xt[row * 16 + 2 * q + 1];
                uint4 u;
                u.x = p2(v0.x, v0.y);
                u.y = p2(v0.z, v0.w);
                u.z = p2(v1.x, v1.y);
                u.w = p2(v1.z, v1.w);
                *reinterpret_cast<uint4*>(sm + XT_U + row * XP + 4 * q) = u;
            }
        }
        __syncthreads();   // (1) x visible; prior-rep HT reads done

        // ---- GEMM1: rows [32mg,+32) x hid cols [64nh,+64), K=64 ----
        float C1[2][8][4];
        #pragma unroll
        for (int mt = 0; mt < 2; mt++)
            #pragma unroll
            for (int t1 = 0; t1 < 8; t1++)
                #pragma unroll
                for (int r = 0; r < 4; r++) C1[mt][t1][r] = 0.0f;

        #pragma unroll
        for (int s = 0; s < 4; s++) {          // k16 steps
            uint4 A0, A1;
            ldsm4(A0, aX + s * 32);
            ldsm4(A1, aX + s * 32 + 16 * XPB);
            #pragma unroll
            for (int tp = 0; tp < 4; tp++) {   // pairs of n-tiles
                uint4 Bv;
                ldsm4(Bv, bW1 + tp * 16 * XPB + s * 32);
                mma16(C1[0][2 * tp],     A0, Bv.x, Bv.y);
                mma16(C1[0][2 * tp + 1], A0, Bv.z, Bv.w);
                mma16(C1[1][2 * tp],     A1, Bv.x, Bv.y);
                mma16(C1[1][2 * tp + 1], A1, Bv.z, Bv.w);
            }
        }

        // ---- epilogue1: bias + ELU -> fp16 -> Ht ----
        #pragma unroll
        for (int mt = 0; mt < 2; mt++) {
            int r0 = mg * 32 + mt * 16;
            #pragma unroll
            for (int t1 = 0; t1 < 8; t1++) {
                int colA = nh * 64 + t1 * 8 + 2 * tc;
                float bA = b1s[colA], bB = b1s[colA + 1];
                float v0 = eluf(C1[mt][t1][0] + bA);
                float v1 = eluf(C1[mt][t1][1] + bB);
                float v2 = eluf(C1[mt][t1][2] + bA);
                float v3 = eluf(C1[mt][t1][3] + bB);
                int cu = nh * 32 + t1 * 4 + tc;
                sm[HT_U + (r0 + g) * HP + cu]     = p2(v0, v1);
                sm[HT_U + (r0 + 8 + g) * HP + cu] = p2(v2, v3);
            }
        }
        __syncthreads();   // (2) Ht complete

        // ---- GEMM2: rows [32mg,+32) x out cols [32nh,+32), K=128 ----
        float C2[2][4][4];
        #pragma unroll
        for (int mt = 0; mt < 2; mt++)
            #pragma unroll
            for (int t2 = 0; t2 < 4; t2++)
                #pragma unroll
                for (int r = 0; r < 4; r++) C2[mt][t2][r] = 0.0f;

        #pragma unroll
        for (int s = 0; s < 8; s++) {
            uint4 A0, A1;
            ldsm4(A0, aH + s * 32);
            ldsm4(A1, aH + s * 32 + 16 * HPB);
            #pragma unroll
            for (int tp = 0; tp < 2; tp++) {
                uint4 Bv;
                ldsm4(Bv, bW2 + tp * 16 * HPB + s * 32);
                mma16(C2[0][2 * tp],     A0, Bv.x, Bv.y);
                mma16(C2[0][2 * tp + 1], A0, Bv.z, Bv.w);
                mma16(C2[1][2 * tp],     A1, Bv.x, Bv.y);
                mma16(C2[1][2 * tp + 1], A1, Bv.z, Bv.w);
            }
        }

        // ---- epilogue2: + b2 -> out[b, head, :] ----
        #pragma unroll
        for (int mt = 0; mt < 2; mt++) {
            const size_t rbase = mbase + (size_t)rep * MT + mg * 32 + mt * 16 + g;
            #pragma unroll
            for (int half = 0; half < 2; half++) {
                const size_t off = (rbase + 8 * half) * (NHEAD * OUT_SZ)
                                 + (size_t)head * OUT_SZ;
                #pragma unroll
                for (int t2 = 0; t2 < 4; t2++) {
                    int col = nh * 32 + t2 * 8 + 2 * tc;
                    float2 o;
                    o.x = C2[mt][t2][half * 2 + 0] + b2s[col];
                    o.y = C2[mt][t2][half * 2 + 1] + b2s[col + 1];
                    *reinterpret_cast<float2*>(out + off + col) = o;
                }
            }
        }
        // staging x for rep+1 before sync(1) is safe: every warp reaching it has
        // passed sync(2) of this rep, and all XT reads (GEMM1) precede sync(2);
        // HT reads (GEMM2) finish before the *next* epilogue1 because sync(1)
        // of rep+1 orders them.
    }
}

// ---------------- launch ----------------
extern "C" void kernel_launch(void* const* d_in, const int* in_sizes, int n_in,
                              void* d_out, int out_size)
{
    const float* x  = (const float*)d_in[0];
    const float* W1 = (const float*)d_in[1];
    const float* b1 = (const float*)d_in[2];
    const float* W2 = (const float*)d_in[3];
    const float* b2 = (const float*)d_in[4];
    float* out = (float*)d_out;

    int B = in_sizes[0] / IN_SZ;            // 131072
    int ytiles = B / (MT * REPS);           // 256

    cudaFuncSetAttribute(mlp16_kernel,
                         cudaFuncAttributeMaxDynamicSharedMemorySize, SMEM_BYTES);
    mlp16_kernel<<<dim3(NHEAD, ytiles), NTHREADS, SMEM_BYTES>>>(x, W1, b1, W2, b2, out);
}